// round 15
// baseline (speedup 1.0000x reference)
#include <cuda_runtime.h>
#include <cstdint>

#define D 50
#define H1 17
#define H3 10
#define WARPS_PER_BLOCK 6

// Collapsed operators, computed once per launch by block 0.
__device__ float g_v[D];
__device__ float g_u2[D];
__device__ float g_U4[D * 2];
__device__ float g_c[3];
__device__ unsigned int g_flag;   // reset to 0 by a memset node each replay

// rootid may be int32 (JAX x64 disabled) or int64. Detect via sentinel check.
__device__ __forceinline__ long long load_root(const void* p, int i, bool is32) {
    if (is32) return (long long)((const int*)p)[i];
    return ((const long long*)p)[i];
}

__device__ __forceinline__ uint32_t smem_addr_u32(const void* p) {
    return (uint32_t)__cvta_generic_to_shared(p);
}

// Dynamic smem layout (float indices):
//   [0  .. 64)    sv    : v vector (50 used)
//   [64 .. 98)    sW34  : W3@W4 intermediates (block 0 only)
//   [98 .. 100)   sb34
//   [104.. 116)   mbarriers (byte 416.., 8B per warp)
//   [128.. )      per-warp session buffers (L*D floats each)
extern __shared__ float s_dyn[];

__global__ __launch_bounds__(32 * WARPS_PER_BLOCK) void fused_kernel(
    const float* __restrict__ emd,
    const void* __restrict__ rootid,
    const int* __restrict__ kptr,
    const float* __restrict__ atte,
    const float* __restrict__ W1, const float* __restrict__ b1,
    const float* __restrict__ W2, const float* __restrict__ b2,
    const float* __restrict__ W3, const float* __restrict__ b3,
    const float* __restrict__ W4, const float* __restrict__ b4,
    float* __restrict__ out,
    int S, int Nspans, int L) {
    float* sv = s_dyn;
    float* sW34 = s_dyn + 64;
    float* sb34 = s_dyn + 98;

    int tid = threadIdx.x;
    int warp = tid >> 5, lane = tid & 31;

    uint32_t mbar = smem_addr_u32(s_dyn) + 416 + warp * 8;
    if (lane == 0) {
        asm volatile("mbarrier.init.shared.b64 [%0], 1;" :: "r"(mbar) : "memory");
    }
    __syncthreads();   // all mbarriers initialized

    int s = blockIdx.x * WARPS_PER_BLOCK + warp;
    bool active = (s < S);
    float* srow = s_dyn + 128 + warp * (L * D);

    // ============ phase 1: kick off the DRAM stream ASAP (per warp) ==========
    int len = 0, k = 0;
    if (active) {
        bool is32 = (((const int*)rootid)[S - 1] == Nspans);
        long long start = (s == 0) ? 0LL : load_root(rootid, s - 1, is32);
        long long end = load_root(rootid, s, is32);
        len = (int)(end - start);
        if (len > L) len = L;
        if (len > 32) len = 32;
        if (len < 0) len = 0;
        k = *kptr;
        if (k > len) k = len;
        if (k < 0) k = 0;

        size_t baseByte = (size_t)start * D * sizeof(float);
        const char* src = (const char*)emd + baseByte;
        unsigned nBytes = (unsigned)(len * D * sizeof(float));
        bool bulk_ok = ((baseByte & 15) == 0);
        unsigned bulkBytes = bulk_ok ? (nBytes & ~15u) : 0u;

        if (lane == 0) {
            if (bulkBytes > 0) {
                asm volatile("mbarrier.arrive.expect_tx.shared.b64 _, [%0], %1;"
                             :: "r"(mbar), "r"(bulkBytes) : "memory");
                asm volatile(
                    "cp.async.bulk.shared::cta.global.mbarrier::complete_tx::bytes "
                    "[%0], [%1], %2, [%3];"
                    :: "r"(smem_addr_u32(srow)), "l"(src), "r"(bulkBytes), "r"(mbar)
                    : "memory");
            } else {
                asm volatile("mbarrier.arrive.shared.b64 _, [%0];"
                             :: "r"(mbar) : "memory");
            }
        }
        for (unsigned t = (bulkBytes >> 2) + lane; t < (nBytes >> 2); t += 32)
            srow[t] = __ldg((const float*)src + t);
    }

    // ===== phase 2 (block 0 ONLY): collapsed operators -> globals, flag =====
    if (blockIdx.x == 0) {
        if (tid < 34) {
            int j = tid >> 1, p = tid & 1;
            float a = 0.f;
#pragma unroll
            for (int m = 0; m < H3; ++m)
                a = fmaf(__ldg(W3 + j * H3 + m), __ldg(W4 + m * 2 + p), a);
            sW34[tid] = a;
        } else if (tid < 36) {
            int p = tid & 1;
            float a = 0.f;
#pragma unroll
            for (int m = 0; m < H3; ++m)
                a = fmaf(__ldg(b3 + m), __ldg(W4 + m * 2 + p), a);
            sb34[p] = a;
        }
        for (int d = warp; d < D; d += WARPS_PER_BLOCK) {
            const float* row = atte + d * D;
            float a = row[lane] + ((lane < D - 32) ? row[32 + lane] : 0.0f);
#pragma unroll
            for (int o = 16; o; o >>= 1) a += __shfl_xor_sync(0xFFFFFFFFu, a, o);
            if (lane == 0) g_v[d] = a;
        }
        __syncthreads();

        if (tid < D) {
            float a = 0.f;
#pragma unroll
            for (int j = 0; j < H1; ++j)
                a = fmaf(__ldg(W1 + tid * H1 + j), __ldg(W2 + j), a);
            g_u2[tid] = a;
        } else if (tid == D) {
            float a = __ldg(b2);
#pragma unroll
            for (int j = 0; j < H1; ++j) a = fmaf(__ldg(b1 + j), __ldg(W2 + j), a);
            g_c[0] = a;
        } else if (tid < 53) {
            int p = tid - 51;
            float a = __ldg(b4 + p) + sb34[p];
#pragma unroll
            for (int j = 0; j < H1; ++j) a = fmaf(__ldg(b1 + j), sW34[j * 2 + p], a);
            g_c[1 + p] = a;
        }
        if (tid >= 64 && tid < 164) {
            int q = tid - 64;
            int d = q >> 1, p = q & 1;
            float a = 0.f;
#pragma unroll
            for (int j = 0; j < H1; ++j)
                a = fmaf(__ldg(W1 + d * H1 + j), sW34[j * 2 + p], a);
            g_U4[q] = a;
        }
        __syncthreads();
        __threadfence();
        if (tid == 0) {
            unsigned one = 1u;
            asm volatile("st.release.gpu.global.u32 [%0], %1;"
                         :: "l"(&g_flag), "r"(one) : "memory");
        }
    }

    // ================= phase 3: wait for bulk completion (per warp) ==========
    if (active) {
        uint32_t done;
        asm volatile(
            "{\n\t"
            ".reg .pred p;\n\t"
            "mbarrier.try_wait.parity.acquire.cta.shared::cta.b64 p, [%1], 0;\n\t"
            "selp.b32 %0, 1, 0, p;\n\t"
            "}"
            : "=r"(done) : "r"(mbar) : "memory");
        if (!done) {
            asm volatile(
                "{\n\t"
                ".reg .pred P1;\n\t"
                "WAIT_LOOP_%=:\n\t"
                "mbarrier.try_wait.parity.acquire.cta.shared::cta.b64 P1, [%0], 0, 0x989680;\n\t"
                "@P1 bra.uni WAIT_DONE_%=;\n\t"
                "bra.uni WAIT_LOOP_%=;\n\t"
                "WAIT_DONE_%=:\n\t"
                "}"
                :: "r"(mbar) : "memory");
        }
    }

    // ===== phase 3b: leader-only flag wait (usually already set) =====
    if (tid == 0) {
        unsigned f;
        asm volatile("ld.acquire.gpu.global.u32 %0, [%1];"
                     : "=r"(f) : "l"(&g_flag) : "memory");
        unsigned backoff = 128;
        while (f == 0u) {
            __nanosleep(backoff);
            if (backoff < 1024u) backoff <<= 1;
            asm volatile("ld.acquire.gpu.global.u32 %0, [%1];"
                         : "=r"(f) : "l"(&g_flag) : "memory");
        }
    }
    __syncthreads();   // propagate acquired writes block-wide
    if (tid < D) sv[tid] = g_v[tid];
    __syncthreads();   // sv visible block-wide

    if (!active) return;

    // ---- per-row score: dot(row, v); lane i = row i; 4 independent chains ----
    float score = 0.0f;
    if (lane < len) {
        const float2* row = (const float2*)&srow[lane * D];
        const float2* vv = (const float2*)sv;
        float s0 = 0.f, s1 = 0.f, s2 = 0.f, s3 = 0.f;
#pragma unroll
        for (int j = 0; j < 24; j += 4) {
            float2 r0 = row[j], r1 = row[j + 1], r2 = row[j + 2], r3 = row[j + 3];
            float2 w0 = vv[j], w1 = vv[j + 1], w2 = vv[j + 2], w3 = vv[j + 3];
            s0 = fmaf(r0.x, w0.x, s0); s0 = fmaf(r0.y, w0.y, s0);
            s1 = fmaf(r1.x, w1.x, s1); s1 = fmaf(r1.y, w1.y, s1);
            s2 = fmaf(r2.x, w2.x, s2); s2 = fmaf(r2.y, w2.y, s2);
            s3 = fmaf(r3.x, w3.x, s3); s3 = fmaf(r3.y, w3.y, s3);
        }
        {
            float2 r = row[24], w = vv[24];
            s0 = fmaf(r.x, w.x, s0); s0 = fmaf(r.y, w.y, s0);
        }
        score = (s0 + s1) + (s2 + s3);
    }

    // ---- top-k selection, tie -> lowest row index (stable-sort semantics) ----
    unsigned key;
    {
        unsigned ub = __float_as_uint(score);
        key = (ub & 0x80000000u) ? ~ub : (ub | 0x80000000u);  // order-preserving map
    }
    unsigned cand = (len >= 32) ? 0xFFFFFFFFu : ((1u << len) - 1u);
    unsigned sel = 0u;
    for (int r = 0; r < k; ++r) {
        unsigned mykey = ((cand >> lane) & 1u) ? key : 0u;
        unsigned mx = __reduce_max_sync(0xFFFFFFFFu, mykey);
        unsigned winners = __ballot_sync(0xFFFFFFFFu,
                                         (mykey == mx) && ((cand >> lane) & 1u));
        if (winners == 0u) break;
        int w = __ffs(winners) - 1;
        sel |= 1u << w;
        cand &= ~(1u << w);
    }

    // ---- sum selected rows; lane j owns dims j and j+32 ----
    float a0 = 0.f, a1 = 0.f;
    unsigned m = sel;
    bool hi_ok = (lane < D - 32);
    while (m) {
        int i = __ffs(m) - 1;
        m &= m - 1;
        const float* row = &srow[i * D];
        a0 += row[lane];                       // conflict-free: consecutive banks
        if (hi_ok) a1 += row[lane + 32];
    }

    // ---- collapsed linear head: 3 dots over 50 dims (weights via L1-hit LDG) ----
    float pl = a0 * g_u2[lane];
    float p0 = a0 * g_U4[lane * 2 + 0];
    float p1 = a0 * g_U4[lane * 2 + 1];
    if (hi_ok) {
        pl = fmaf(a1, g_u2[lane + 32], pl);
        p0 = fmaf(a1, g_U4[(lane + 32) * 2 + 0], p0);
        p1 = fmaf(a1, g_U4[(lane + 32) * 2 + 1], p1);
    }
#pragma unroll
    for (int o = 16; o; o >>= 1) {
        pl += __shfl_xor_sync(0xFFFFFFFFu, pl, o);
        p0 += __shfl_xor_sync(0xFFFFFFFFu, p0, o);
        p1 += __shfl_xor_sync(0xFFFFFFFFu, p1, o);
    }
    if (lane == 0) {
        out[s] = pl + g_c[0];                // logits [S,1]
        out[S + 2 * s + 0] = p0 + g_c[1];    // h2 [S,2]
        out[S + 2 * s + 1] = p1 + g_c[2];
    }
}

extern "C" void kernel_launch(void* const* d_in, const int* in_sizes, int n_in,
                              void* d_out, int out_size) {
    const float* emd = (const float*)d_in[0];
    const void* rootid = d_in[1];
    const float* atte = (const float*)d_in[2];
    const float* W1 = (const float*)d_in[3];
    const float* b1 = (const float*)d_in[4];
    const float* W2 = (const float*)d_in[5];
    const float* b2 = (const float*)d_in[6];
    const float* W3 = (const float*)d_in[7];
    const float* b3 = (const float*)d_in[8];
    const float* W4 = (const float*)d_in[9];
    const float* b4 = (const float*)d_in[10];
    const int* kptr = (const int*)d_in[11];
    float* out = (float*)d_out;

    int S = in_sizes[1];
    int Nspans = in_sizes[0] / D;
    int L = Nspans / S;  // uniform session length
    if (L < 1) L = 1;
    if (L > 32) L = 32;  // lane=row scheme bound (bench: L=20)

    // Maximize resident blocks: prefer smem over L1 carveout.
    static bool attr_done = false;
    if (!attr_done) {
        cudaFuncSetAttribute(fused_kernel,
                             cudaFuncAttributePreferredSharedMemoryCarveout, 100);
        attr_done = true;
    }

    // Reset the operator-ready flag (tiny memset node; graph-legal).
    void* flag_addr = nullptr;
    cudaGetSymbolAddress(&flag_addr, g_flag);
    cudaMemsetAsync(flag_addr, 0, sizeof(unsigned int));

    // 512 B header (sv + scratch + mbarriers) + per-warp session buffers
    size_t dynBytes = 512 + (size_t)WARPS_PER_BLOCK * L * D * sizeof(float);
    int blocks = (S + WARPS_PER_BLOCK - 1) / WARPS_PER_BLOCK;
    fused_kernel<<<blocks, 32 * WARPS_PER_BLOCK, dynBytes>>>(
        emd, rootid, kptr, atte, W1, b1, W2, b2, W3, b3, W4, b4,
        out, S, Nspans, L);
}

// round 16
// speedup vs baseline: 1.2154x; 1.2154x over previous
#include <cuda_runtime.h>
#include <cstdint>

#define D 50
#define H1 17
#define H3 10
#define WARPS_PER_BLOCK 6

// Precomputed collapsed-linear operators (written by precompute_kernel)
__device__ float g_v[D];        // atte.sum(axis=1)
__device__ float g_u2[D];       // W1 @ W2            -> logits direction
__device__ float g_U4[D * 2];   // W1 @ W3 @ W4       -> h2 directions
__device__ float g_c[3];        // [b1@W2+b2, ((b1@W3+b3)@W4+b4)[0..1]]

// Wide-and-shallow precompute: 52 blocks x 1 warp, every block independent.
//   blocks 0..49 : v[b] = row-sum of atte row b
//   block  50    : u2 = W1@W2 (+ c0)
//   block  51    : W34 = W3@W4 -> U4 = W1@W34 (+ c1, c2)
__global__ __launch_bounds__(32) void precompute_kernel(
    const float* __restrict__ atte,
    const float* __restrict__ W1, const float* __restrict__ b1,
    const float* __restrict__ W2, const float* __restrict__ b2,
    const float* __restrict__ W3, const float* __restrict__ b3,
    const float* __restrict__ W4, const float* __restrict__ b4) {
    int b = blockIdx.x;
    int lane = threadIdx.x;

    if (b < D) {
        // one atte row-sum per block, coalesced
        const float* row = atte + b * D;
        float a = row[lane] + ((lane < D - 32) ? row[32 + lane] : 0.0f);
#pragma unroll
        for (int o = 16; o; o >>= 1) a += __shfl_xor_sync(0xFFFFFFFFu, a, o);
        if (lane == 0) g_v[b] = a;
    } else if (b == D) {
        // u2[d] = sum_j W1[d][j] * W2[j]; c0
        {
            float a = 0.f;
#pragma unroll
            for (int j = 0; j < H1; ++j)
                a = fmaf(__ldg(W1 + lane * H1 + j), __ldg(W2 + j), a);
            g_u2[lane] = a;
        }
        if (lane < D - 32) {
            int d = lane + 32;
            float a = 0.f;
#pragma unroll
            for (int j = 0; j < H1; ++j)
                a = fmaf(__ldg(W1 + d * H1 + j), __ldg(W2 + j), a);
            g_u2[d] = a;
        }
        if (lane == 0) {
            float a = __ldg(b2);
#pragma unroll
            for (int j = 0; j < H1; ++j) a = fmaf(__ldg(b1 + j), __ldg(W2 + j), a);
            g_c[0] = a;
        }
    } else {
        // U4 = W1 @ (W3 @ W4); c1, c2
        __shared__ float sW34[H1 * 2];
        __shared__ float sb34[2];
        if (lane < H1) {
#pragma unroll
            for (int p = 0; p < 2; ++p) {
                float a = 0.f;
#pragma unroll
                for (int m = 0; m < H3; ++m)
                    a = fmaf(__ldg(W3 + lane * H3 + m), __ldg(W4 + m * 2 + p), a);
                sW34[lane * 2 + p] = a;
            }
        } else if (lane == H1) {
#pragma unroll
            for (int p = 0; p < 2; ++p) {
                float a = 0.f;
#pragma unroll
                for (int m = 0; m < H3; ++m)
                    a = fmaf(__ldg(b3 + m), __ldg(W4 + m * 2 + p), a);
                sb34[p] = a;
            }
        }
        __syncwarp();
#pragma unroll
        for (int p = 0; p < 2; ++p) {
            float a = 0.f;
#pragma unroll
            for (int j = 0; j < H1; ++j)
                a = fmaf(__ldg(W1 + lane * H1 + j), sW34[j * 2 + p], a);
            g_U4[lane * 2 + p] = a;
        }
        if (lane < D - 32) {
            int d = lane + 32;
#pragma unroll
            for (int p = 0; p < 2; ++p) {
                float a = 0.f;
#pragma unroll
                for (int j = 0; j < H1; ++j)
                    a = fmaf(__ldg(W1 + d * H1 + j), sW34[j * 2 + p], a);
                g_U4[d * 2 + p] = a;
            }
        }
        if (lane == 0) {
#pragma unroll
            for (int p = 0; p < 2; ++p) {
                float a = __ldg(b4 + p) + sb34[p];
#pragma unroll
                for (int j = 0; j < H1; ++j)
                    a = fmaf(__ldg(b1 + j), sW34[j * 2 + p], a);
                g_c[1 + p] = a;
            }
        }
    }
}

// rootid may be int32 (JAX x64 disabled) or int64. Detect via sentinel check.
__device__ __forceinline__ long long load_root(const void* p, int i, bool is32) {
    if (is32) return (long long)((const int*)p)[i];
    return ((const long long*)p)[i];
}

__device__ __forceinline__ uint32_t smem_addr_u32(const void* p) {
    return (uint32_t)__cvta_generic_to_shared(p);
}

// Dynamic smem layout (16B-aligned sections):
//   [0   .. 256)                 : sv (v vector, 50 floats used)
//   [256 .. 256+8*W)             : per-warp mbarrier (8B each)
//   [320 .. 320 + w*4*L*D .. )   : per-warp session buffer (L*D floats)
extern __shared__ float s_dyn[];

__global__ __launch_bounds__(32 * WARPS_PER_BLOCK) void session_kernel(
    const float* __restrict__ emd,
    const void* __restrict__ rootid,
    const int* __restrict__ kptr,
    float* __restrict__ out,
    int S, int Nspans, int L) {
    float* sv = s_dyn;
    int tid = threadIdx.x;
    if (tid < D) sv[tid] = g_v[tid];

    int warp = tid >> 5, lane = tid & 31;
    uint32_t mbar = smem_addr_u32(s_dyn) + 256 + warp * 8;
    if (lane == 0) {
        asm volatile("mbarrier.init.shared.b64 [%0], 1;" :: "r"(mbar) : "memory");
    }
    __syncthreads();   // sv visible + all mbarriers initialized

    int s = blockIdx.x * WARPS_PER_BLOCK + warp;
    if (s >= S) return;

    float* srow = s_dyn + 80 + warp * (L * D);   // 320 bytes = 80 floats

    bool is32 = (((const int*)rootid)[S - 1] == Nspans);
    long long start = (s == 0) ? 0LL : load_root(rootid, s - 1, is32);
    long long end = load_root(rootid, s, is32);
    int len = (int)(end - start);
    if (len > L) len = L;
    if (len > 32) len = 32;
    if (len < 0) len = 0;
    int k = *kptr;
    if (k > len) k = len;
    if (k < 0) k = 0;

    // ---- stage session rows into smem via ONE bulk copy (UBLKCP) ----
    size_t baseByte = (size_t)start * D * sizeof(float);
    const char* src = (const char*)emd + baseByte;
    unsigned nBytes = (unsigned)(len * D * sizeof(float));
    bool bulk_ok = ((baseByte & 15) == 0);
    unsigned bulkBytes = bulk_ok ? (nBytes & ~15u) : 0u;

    if (lane == 0) {
        if (bulkBytes > 0) {
            asm volatile("mbarrier.arrive.expect_tx.shared.b64 _, [%0], %1;"
                         :: "r"(mbar), "r"(bulkBytes) : "memory");
            asm volatile(
                "cp.async.bulk.shared::cta.global.mbarrier::complete_tx::bytes "
                "[%0], [%1], %2, [%3];"
                :: "r"(smem_addr_u32(srow)), "l"(src), "r"(bulkBytes), "r"(mbar)
                : "memory");
        } else {
            asm volatile("mbarrier.arrive.shared.b64 _, [%0];"
                         :: "r"(mbar) : "memory");
        }
    }
    // tail / unaligned fallback words via plain loads
    for (unsigned t = (bulkBytes >> 2) + lane; t < (nBytes >> 2); t += 32)
        srow[t] = __ldg((const float*)src + t);
    __syncwarp();

    // ---- wait for bulk completion (phase 0) ----
    {
        uint32_t done;
        asm volatile(
            "{\n\t"
            ".reg .pred p;\n\t"
            "mbarrier.try_wait.parity.acquire.cta.shared::cta.b64 p, [%1], 0;\n\t"
            "selp.b32 %0, 1, 0, p;\n\t"
            "}"
            : "=r"(done) : "r"(mbar) : "memory");
        if (!done) {
            asm volatile(
                "{\n\t"
                ".reg .pred P1;\n\t"
                "WAIT_LOOP_%=:\n\t"
                "mbarrier.try_wait.parity.acquire.cta.shared::cta.b64 P1, [%0], 0, 0x989680;\n\t"
                "@P1 bra.uni WAIT_DONE_%=;\n\t"
                "bra.uni WAIT_LOOP_%=;\n\t"
                "WAIT_DONE_%=:\n\t"
                "}"
                :: "r"(mbar) : "memory");
        }
    }

    // ---- per-row score: dot(row, v); lane i = row i; 4 independent chains ----
    float score = 0.0f;
    if (lane < len) {
        const float2* row = (const float2*)&srow[lane * D];
        const float2* vv = (const float2*)sv;
        float s0 = 0.f, s1 = 0.f, s2 = 0.f, s3 = 0.f;
#pragma unroll
        for (int j = 0; j < 24; j += 4) {
            float2 r0 = row[j], r1 = row[j + 1], r2 = row[j + 2], r3 = row[j + 3];
            float2 w0 = vv[j], w1 = vv[j + 1], w2 = vv[j + 2], w3 = vv[j + 3];
            s0 = fmaf(r0.x, w0.x, s0); s0 = fmaf(r0.y, w0.y, s0);
            s1 = fmaf(r1.x, w1.x, s1); s1 = fmaf(r1.y, w1.y, s1);
            s2 = fmaf(r2.x, w2.x, s2); s2 = fmaf(r2.y, w2.y, s2);
            s3 = fmaf(r3.x, w3.x, s3); s3 = fmaf(r3.y, w3.y, s3);
        }
        {
            float2 r = row[24], w = vv[24];
            s0 = fmaf(r.x, w.x, s0); s0 = fmaf(r.y, w.y, s0);
        }
        score = (s0 + s1) + (s2 + s3);
    }

    // ---- top-k selection, tie -> lowest row index (stable-sort semantics) ----
    unsigned key;
    {
        unsigned ub = __float_as_uint(score);
        key = (ub & 0x80000000u) ? ~ub : (ub | 0x80000000u);  // order-preserving map
    }
    unsigned cand = (len >= 32) ? 0xFFFFFFFFu : ((1u << len) - 1u);
    unsigned sel = 0u;
    for (int r = 0; r < k; ++r) {
        unsigned mykey = ((cand >> lane) & 1u) ? key : 0u;
        unsigned mx = __reduce_max_sync(0xFFFFFFFFu, mykey);
        unsigned winners = __ballot_sync(0xFFFFFFFFu,
                                         (mykey == mx) && ((cand >> lane) & 1u));
        if (winners == 0u) break;
        int w = __ffs(winners) - 1;
        sel |= 1u << w;
        cand &= ~(1u << w);
    }

    // ---- sum selected rows; lane j owns dims j and j+32 ----
    float a0 = 0.f, a1 = 0.f;
    unsigned m = sel;
    bool hi_ok = (lane < D - 32);
    while (m) {
        int i = __ffs(m) - 1;
        m &= m - 1;
        const float* row = &srow[i * D];
        a0 += row[lane];                       // conflict-free: consecutive banks
        if (hi_ok) a1 += row[lane + 32];
    }

    // ---- collapsed linear head: 3 dots over 50 dims (weights via L1-hit LDG) ----
    float pl = a0 * g_u2[lane];
    float p0 = a0 * g_U4[lane * 2 + 0];
    float p1 = a0 * g_U4[lane * 2 + 1];
    if (hi_ok) {
        pl = fmaf(a1, g_u2[lane + 32], pl);
        p0 = fmaf(a1, g_U4[(lane + 32) * 2 + 0], p0);
        p1 = fmaf(a1, g_U4[(lane + 32) * 2 + 1], p1);
    }
#pragma unroll
    for (int o = 16; o; o >>= 1) {
        pl += __shfl_xor_sync(0xFFFFFFFFu, pl, o);
        p0 += __shfl_xor_sync(0xFFFFFFFFu, p0, o);
        p1 += __shfl_xor_sync(0xFFFFFFFFu, p1, o);
    }
    if (lane == 0) {
        out[s] = pl + g_c[0];                // logits [S,1]
        out[S + 2 * s + 0] = p0 + g_c[1];    // h2 [S,2]
        out[S + 2 * s + 1] = p1 + g_c[2];
    }
}

extern "C" void kernel_launch(void* const* d_in, const int* in_sizes, int n_in,
                              void* d_out, int out_size) {
    const float* emd = (const float*)d_in[0];
    const void* rootid = d_in[1];
    const float* atte = (const float*)d_in[2];
    const float* W1 = (const float*)d_in[3];
    const float* b1 = (const float*)d_in[4];
    const float* W2 = (const float*)d_in[5];
    const float* b2 = (const float*)d_in[6];
    const float* W3 = (const float*)d_in[7];
    const float* b3 = (const float*)d_in[8];
    const float* W4 = (const float*)d_in[9];
    const float* b4 = (const float*)d_in[10];
    const int* kptr = (const int*)d_in[11];
    float* out = (float*)d_out;

    int S = in_sizes[1];
    int Nspans = in_sizes[0] / D;
    int L = Nspans / S;  // uniform session length
    if (L < 1) L = 1;
    if (L > 32) L = 32;  // lane=row scheme bound (bench: L=20)

    // Wide-and-shallow precompute: 52 independent 1-warp blocks (<1.5 us)
    precompute_kernel<<<D + 2, 32>>>(atte, W1, b1, W2, b2, W3, b3, W4, b4);

    // Maximize resident blocks: prefer smem over L1 carveout.
    static bool attr_done = false;
    if (!attr_done) {
        cudaFuncSetAttribute(session_kernel,
                             cudaFuncAttributePreferredSharedMemoryCarveout, 100);
        attr_done = true;
    }

    // 320 B header (sv + mbarriers) + per-warp session buffers
    size_t dynBytes = 320 + (size_t)WARPS_PER_BLOCK * L * D * sizeof(float);
    int blocks = (S + WARPS_PER_BLOCK - 1) / WARPS_PER_BLOCK;
    session_kernel<<<blocks, 32 * WARPS_PER_BLOCK, dynBytes>>>(
        emd, rootid, kptr, out, S, Nspans, L);
}